// round 1
// baseline (speedup 1.0000x reference)
#include <cuda_runtime.h>

// ---------------------------------------------------------------------------
// LapImage: fused 4-level trilinear grid_sample (align_corners=True, zeros pad)
//   coords: [B=4, 96,96,96, 3] float32, values in [-1, 1)
//   img0..img3: [C=3, D=32, H, W], H=W in {32, 64, 128, 256}
//   out: [B, 3, 96,96,96] float32 = sum over levels of trilinear samples
//
// Strategy:
//   1) repack each volume from [3, D, H, W] to channels-last padded [D, H, W, 4]
//      in a __device__ scratch buffer -> each (z,y,x) corner is one aligned
//      float4, each x-corner-pair is 32B contiguous (1-2 L2 sectors).
//   2) one thread per point, fully unrolled over the 4 levels; z interp shared
//      (all levels have D=32). 8x LDG.128 per level.
// All volumes (~45 MB packed) stay resident in L2; kernel is L2-gather bound.
// ---------------------------------------------------------------------------

#define NPTS  (4 * 96 * 96 * 96)   // 3,538,944
#define PLANE (96 * 96 * 96)       // 884,736

// packed volumes: lvl0 32^3=32768 vox, lvl1 32*64*64=131072,
// lvl2 32*128*128=524288, lvl3 32*256*256=2097152 -> 2,785,280 float4 (44.6 MB)
__device__ float4 g_vol[2785280];

__global__ __launch_bounds__(256)
void repack_kernel(const float* __restrict__ src, int voff, int n) {
    int i = blockIdx.x * blockDim.x + threadIdx.x;
    if (i >= n) return;
    float4 v;
    v.x = src[i];            // channel 0 plane
    v.y = src[n + i];        // channel 1 plane
    v.z = src[2 * n + i];    // channel 2 plane
    v.w = 0.0f;
    g_vol[voff + i] = v;
}

__global__ __launch_bounds__(256)
void sample_kernel(const float* __restrict__ coords, float* __restrict__ out) {
    int p = blockIdx.x * blockDim.x + threadIdx.x;
    if (p >= NPTS) return;

    float gx = coords[3 * p + 0];
    float gy = coords[3 * p + 1];
    float gz = coords[3 * p + 2];

    // z dimension identical across all levels (D = 32)
    float iz  = (gz + 1.0f) * 15.5f;          // 0.5 * (32 - 1)
    float z0f = floorf(iz);
    float wz1 = iz - z0f;
    float wz0 = 1.0f - wz1;
    int   z0  = (int)z0f;
    z0 = max(0, min(z0, 31));
    int   z1  = min(z0 + 1, 31);

    float ax = 0.0f, ay = 0.0f, az = 0.0f;

    const int offs[4] = {0, 32768, 163840, 688128};

#pragma unroll
    for (int lvl = 0; lvl < 4; ++lvl) {
        const int   HW  = 32 << lvl;             // 32, 64, 128, 256 (H == W)
        const float sc  = 0.5f * (float)(HW - 1);
        const float4* __restrict__ vol = g_vol + offs[lvl];

        float ix  = (gx + 1.0f) * sc;
        float iy  = (gy + 1.0f) * sc;
        float x0f = floorf(ix);
        float y0f = floorf(iy);
        float wx1 = ix - x0f, wx0 = 1.0f - wx1;
        float wy1 = iy - y0f, wy0 = 1.0f - wy1;
        int x0 = (int)x0f; x0 = max(0, min(x0, HW - 1));
        int y0 = (int)y0f; y0 = max(0, min(y0, HW - 1));
        int x1 = min(x0 + 1, HW - 1);
        int y1 = min(y0 + 1, HW - 1);

        int r00 = (z0 * HW + y0) * HW;
        int r01 = (z0 * HW + y1) * HW;
        int r10 = (z1 * HW + y0) * HW;
        int r11 = (z1 * HW + y1) * HW;

        float4 a00 = vol[r00 + x0], b00 = vol[r00 + x1];
        float4 a01 = vol[r01 + x0], b01 = vol[r01 + x1];
        float4 a10 = vol[r10 + x0], b10 = vol[r10 + x1];
        float4 a11 = vol[r11 + x0], b11 = vol[r11 + x1];

        float w00 = wz0 * wy0;
        float w01 = wz0 * wy1;
        float w10 = wz1 * wy0;
        float w11 = wz1 * wy1;

        ax += w00 * (a00.x * wx0 + b00.x * wx1)
            + w01 * (a01.x * wx0 + b01.x * wx1)
            + w10 * (a10.x * wx0 + b10.x * wx1)
            + w11 * (a11.x * wx0 + b11.x * wx1);
        ay += w00 * (a00.y * wx0 + b00.y * wx1)
            + w01 * (a01.y * wx0 + b01.y * wx1)
            + w10 * (a10.y * wx0 + b10.y * wx1)
            + w11 * (a11.y * wx0 + b11.y * wx1);
        az += w00 * (a00.z * wx0 + b00.z * wx1)
            + w01 * (a01.z * wx0 + b01.z * wx1)
            + w10 * (a10.z * wx0 + b10.z * wx1)
            + w11 * (a11.z * wx0 + b11.z * wx1);
    }

    int b  = p / PLANE;
    int pl = p - b * PLANE;
    float* o = out + (size_t)b * (3 * PLANE) + pl;
    o[0]         = ax;
    o[PLANE]     = ay;
    o[2 * PLANE] = az;
}

extern "C" void kernel_launch(void* const* d_in, const int* in_sizes, int n_in,
                              void* d_out, int out_size) {
    const float* coords = (const float*)d_in[0];
    const float* img0   = (const float*)d_in[1];
    const float* img1   = (const float*)d_in[2];
    const float* img2   = (const float*)d_in[3];
    const float* img3   = (const float*)d_in[4];
    float* out = (float*)d_out;

    // repack each level to channels-last padded float4 (same stream -> ordered)
    repack_kernel<<<(32768  + 255) / 256, 256>>>(img0, 0,      32768);
    repack_kernel<<<(131072 + 255) / 256, 256>>>(img1, 32768,  131072);
    repack_kernel<<<(524288 + 255) / 256, 256>>>(img2, 163840, 524288);
    repack_kernel<<<(2097152+ 255) / 256, 256>>>(img3, 688128, 2097152);

    sample_kernel<<<(NPTS + 255) / 256, 256>>>(coords, out);
}

// round 2
// speedup vs baseline: 1.5087x; 1.5087x over previous
#include <cuda_runtime.h>
#include <cuda_fp16.h>

// ---------------------------------------------------------------------------
// LapImage: fused 4-level trilinear grid_sample (align_corners=True)
//   coords: [B=4, 96,96,96, 3] fp32 in [-1, 1)  -> no boundary clamping needed
//   img0..img3: [C=3, D=32, H, W], H=W in {32,64,128,256}
//   out: [B, 3, 96,96,96] fp32 = sum over levels
//
// Round-2 strategy: x-corner-PAIR packed fp16 layout.
//   entry[z][y][x] (16B, aligned) = halves [c0(x),c1(x),c2(x), c0(x+1),c1(x+1),c2(x+1), 0,0]
//   -> one LDG.128 per (z,y) corner row fetches BOTH x corners in exactly ONE
//      32B L2 sector. 4 loads/level, 16 loads/point, 512B of L2 sectors/point.
//   Weights + accumulation stay fp32 (fp16 only quantizes the stored volume,
//   ~1.5e-4 norm rel err << 1e-3 threshold).
// Footprint 2,785,280 x 16B = 44.6 MB -> L2-resident.
// ---------------------------------------------------------------------------

#define NPTS   (4 * 96 * 96 * 96)   // 3,538,944
#define PLANE  (96 * 96 * 96)       // 884,736
#define NVOX   2785280              // 32768 + 131072 + 524288 + 2097152

__device__ uint4 g_vol[NVOX];       // 44.6 MB pair-packed fp16 volumes

__global__ __launch_bounds__(256)
void repack_all_kernel(const float* __restrict__ i0, const float* __restrict__ i1,
                       const float* __restrict__ i2, const float* __restrict__ i3) {
    int i = blockIdx.x * blockDim.x + threadIdx.x;
    if (i >= NVOX) return;

    const float* __restrict__ src;
    int n, base;
    if (i < 32768)        { src = i0; n = 32768;   base = 0;      }
    else if (i < 163840)  { src = i1; n = 131072;  base = 32768;  }
    else if (i < 688128)  { src = i2; n = 524288;  base = 163840; }
    else                  { src = i3; n = 2097152; base = 688128; }

    int li = i - base;
    int j  = min(li + 1, n - 1);    // x+1 neighbor (row-crossing garbage is never sampled)

    __half a0 = __float2half_rn(src[li]);
    __half a1 = __float2half_rn(src[n + li]);
    __half a2 = __float2half_rn(src[2 * n + li]);
    __half b0 = __float2half_rn(src[j]);
    __half b1 = __float2half_rn(src[n + j]);
    __half b2 = __float2half_rn(src[2 * n + j]);

    __half2 p0 = __halves2half2(a0, a1);
    __half2 p1 = __halves2half2(a2, b0);
    __half2 p2 = __halves2half2(b1, b2);
    uint4 v;
    v.x = *(unsigned int*)&p0;
    v.y = *(unsigned int*)&p1;
    v.z = *(unsigned int*)&p2;
    v.w = 0u;
    g_vol[i] = v;
}

__device__ __forceinline__ void acc_pair(uint4 q, float w, float wx0, float wx1,
                                         float& ax, float& ay, float& az) {
    float2 f0 = __half22float2(*(__half2*)&q.x);   // c0(x0), c1(x0)
    float2 f1 = __half22float2(*(__half2*)&q.y);   // c2(x0), c0(x1)
    float2 f2 = __half22float2(*(__half2*)&q.z);   // c1(x1), c2(x1)
    ax = fmaf(w, fmaf(f0.x, wx0, f1.y * wx1), ax);
    ay = fmaf(w, fmaf(f0.y, wx0, f2.x * wx1), ay);
    az = fmaf(w, fmaf(f1.x, wx0, f2.y * wx1), az);
}

__global__ __launch_bounds__(256)
void sample_kernel(const float* __restrict__ coords, float* __restrict__ out) {
    int p = blockIdx.x * blockDim.x + threadIdx.x;
    if (p >= NPTS) return;

    float gx = coords[3 * p + 0];
    float gy = coords[3 * p + 1];
    float gz = coords[3 * p + 2];

    // z dimension identical across all levels (D = 32); coords in [-1,1) -> no low clamp
    float iz  = (gz + 1.0f) * 15.5f;
    float z0f = floorf(iz);
    float wz1 = iz - z0f;
    float wz0 = 1.0f - wz1;
    int   z0  = min((int)z0f, 30);     // defensive; mathematically z0 <= 30
    int   z1  = z0 + 1;

    float ax = 0.0f, ay = 0.0f, az = 0.0f;
    const int offs[4] = {0, 32768, 163840, 688128};

#pragma unroll
    for (int lvl = 0; lvl < 4; ++lvl) {
        const int   HW = 32 << lvl;                // 32, 64, 128, 256
        const float sc = 0.5f * (float)(HW - 1);
        const uint4* __restrict__ vol = g_vol + offs[lvl];

        float ix  = (gx + 1.0f) * sc;
        float iy  = (gy + 1.0f) * sc;
        float x0f = floorf(ix);
        float y0f = floorf(iy);
        float wx1 = ix - x0f, wx0 = 1.0f - wx1;
        float wy1 = iy - y0f, wy0 = 1.0f - wy1;
        int x0 = min((int)x0f, HW - 2);            // pair entry covers x0, x0+1
        int y0 = min((int)y0f, HW - 2);
        int y1 = y0 + 1;

        int r00 = (z0 * HW + y0) * HW + x0;
        int r01 = (z0 * HW + y1) * HW + x0;
        int r10 = (z1 * HW + y0) * HW + x0;
        int r11 = (z1 * HW + y1) * HW + x0;

        uint4 q00 = __ldg(vol + r00);
        uint4 q01 = __ldg(vol + r01);
        uint4 q10 = __ldg(vol + r10);
        uint4 q11 = __ldg(vol + r11);

        acc_pair(q00, wz0 * wy0, wx0, wx1, ax, ay, az);
        acc_pair(q01, wz0 * wy1, wx0, wx1, ax, ay, az);
        acc_pair(q10, wz1 * wy0, wx0, wx1, ax, ay, az);
        acc_pair(q11, wz1 * wy1, wx0, wx1, ax, ay, az);
    }

    int b  = p / PLANE;
    int pl = p - b * PLANE;
    float* o = out + (size_t)b * (3 * PLANE) + pl;
    o[0]         = ax;
    o[PLANE]     = ay;
    o[2 * PLANE] = az;
}

extern "C" void kernel_launch(void* const* d_in, const int* in_sizes, int n_in,
                              void* d_out, int out_size) {
    const float* coords = (const float*)d_in[0];
    const float* img0   = (const float*)d_in[1];
    const float* img1   = (const float*)d_in[2];
    const float* img2   = (const float*)d_in[3];
    const float* img3   = (const float*)d_in[4];
    float* out = (float*)d_out;

    repack_all_kernel<<<(NVOX + 255) / 256, 256>>>(img0, img1, img2, img3);
    sample_kernel<<<(NPTS + 255) / 256, 256>>>(coords, out);
}